// round 11
// baseline (speedup 1.0000x reference)
#include <cuda_runtime.h>
#include <cstdint>

#define C_DIM   256
#define NCODES  256
#define HW_DIM  32768       // 128*256
#define BATCH   4
#define N_TILE  128         // pixels per CTA
#define KC      32          // K-chunk
#define NKB     8           // 256 / 32

// Projection matrix, TF32-rounded, stored in *fragment order* for the GEMM:
// d_Mf[ ((kb*16 + r16)*4 + kk)*32 + lane ][4]
//   lane = g*4 + tg  (g = m%8 within 16-row block half, tg = k%4)
//   component j = half_m + 2*half_k  (a0=(m,k), a1=(m+8,k), a2=(m,k+4), a3=(m+8,k+4))
__device__ float d_Mf[C_DIM * C_DIM];

// ---------------------------------------------------------------------------
// smem (words)
// ---------------------------------------------------------------------------
#define A_WORDS   8192                 // one A stage: 32KB (16 r16 x 4 kk x 32 lanes x 4)
#define B_STRIDE  136                  // 128 + 8 pad -> conflict-free frag reads
#define B_WORDS   (32 * B_STRIDE)      // 4352 words = 17408B
#define SMEM_WORDS (2 * A_WORDS + 2 * B_WORDS)
#define SMEM_BYTES (SMEM_WORDS * 4)    // 100352 B

__device__ __forceinline__ float to_tf32(float x) {
    uint32_t u;
    asm("cvt.rna.tf32.f32 %0, %1;" : "=r"(u) : "f"(x));
    return __uint_as_float(u);
}
__device__ __forceinline__ void mma_tf32(float c[4],
                                         uint32_t a0, uint32_t a1, uint32_t a2, uint32_t a3,
                                         uint32_t b0, uint32_t b1) {
    asm volatile(
        "mma.sync.aligned.m16n8k8.row.col.f32.tf32.tf32.f32 "
        "{%0,%1,%2,%3}, {%4,%5,%6,%7}, {%8,%9}, {%0,%1,%2,%3};"
        : "+f"(c[0]), "+f"(c[1]), "+f"(c[2]), "+f"(c[3])
        : "r"(a0), "r"(a1), "r"(a2), "r"(a3), "r"(b0), "r"(b1));
}
__device__ __forceinline__ void cp_async16(uint32_t smem_addr, const void* g) {
    asm volatile("cp.async.cg.shared.global [%0], [%1], 16;" :: "r"(smem_addr), "l"(g));
}
__device__ __forceinline__ void cp_commit() { asm volatile("cp.async.commit_group;"); }
__device__ __forceinline__ void cp_wait_all() { asm volatile("cp.async.wait_group 0;"); }

// ---------------------------------------------------------------------------
// Kernel 0: M[i][j] = sum_n cb[n][i]*cb[n][j]/||cb[n]||^2, TF32-rounded,
// written directly in GEMM fragment order. Grid (16,16) x 256 threads.
// ---------------------------------------------------------------------------
__global__ void mmat_kernel(const float* __restrict__ cb) {
    __shared__ float s_inv[NCODES];
    __shared__ float sI[NCODES][16];
    __shared__ float sJ[NCODES][16];
    const int I0 = blockIdx.x * 16, J0 = blockIdx.y * 16;
    const int tid = threadIdx.x;

    {   // per-thread inverse norm of code `tid`
        float s = 0.0f;
        const float* row = cb + tid * C_DIM;
        #pragma unroll 8
        for (int c = 0; c < C_DIM; c++) s += row[c] * row[c];
        s_inv[tid] = 1.0f / s;
    }
    __syncthreads();

    for (int e = tid; e < NCODES * 16; e += 256) {
        int n = e >> 4, ii = e & 15;
        sI[n][ii] = cb[n * C_DIM + I0 + ii];
        sJ[n][ii] = cb[n * C_DIM + J0 + ii] * s_inv[n];
    }
    __syncthreads();

    const int ti = tid & 15, tj = tid >> 4;
    float acc = 0.0f;
    #pragma unroll 8
    for (int n = 0; n < NCODES; n++) acc += sI[n][ti] * sJ[n][tj];

    const int i = I0 + ti, j = J0 + tj;
    const int r16 = i >> 4, g = i & 7, hm = (i >> 3) & 1;
    const int kb = j >> 5, kk = (j >> 3) & 3, tg = j & 3, hk = (j >> 2) & 1;
    const int lane = g * 4 + tg;
    const int comp = hm + 2 * hk;
    d_Mf[(((kb * 16 + r16) * 4 + kk) * 32 + lane) * 4 + comp] = to_tf32(acc);
}

// ---------------------------------------------------------------------------
// Kernel 1: out[b][c][p] = sum_k M[c][k] * feat[b][k][p]
// CTA tile 256(M) x 128(N), 512 threads (warps: 4 M x 4 N, each 64x32),
// K chunks of 32, double-buffered. A via contiguous cp.async (frag order),
// B via float4 load + TF32 cvt + padded smem store.
// ---------------------------------------------------------------------------
__global__ void __launch_bounds__(512)
gemm_kernel(const float* __restrict__ feat, float* __restrict__ out) {
    extern __shared__ float smem[];
    float* const Abuf = smem;                       // 2 x A_WORDS
    float* const Bbuf = smem + 2 * A_WORDS;         // 2 x B_WORDS

    const int tid  = threadIdx.x;
    const int lane = tid & 31;
    const int warp = tid >> 5;
    const int g    = lane >> 2;
    const int tg   = lane & 3;
    const int wm   = warp >> 2;          // 0..3, 64 M-rows each
    const int wn   = warp & 3;           // 0..3, 32 pixels each

    const int p0 = blockIdx.x * N_TILE;
    const int b  = blockIdx.y;
    const float* Bg = feat + (size_t)b * C_DIM * HW_DIM + p0;

    // B loader: row r = tid>>4 (0..31), float4 cols q and q+16
    const int b_r = tid >> 4;
    const int b_q = tid & 15;

    const uint32_t as_base = (uint32_t)__cvta_generic_to_shared(Abuf);

    float acc[4][4][4];
    #pragma unroll
    for (int mi = 0; mi < 4; mi++)
        #pragma unroll
        for (int ni = 0; ni < 4; ni++)
            #pragma unroll
            for (int q = 0; q < 4; q++) acc[mi][ni][q] = 0.0f;

    // ---- prologue: stage 0 ----
    {
        const char* Asrc = (const char*)d_Mf;
        #pragma unroll
        for (int pass = 0; pass < 4; pass++)
            cp_async16(as_base + (uint32_t)(tid * 16 + pass * 8192),
                       Asrc + tid * 16 + pass * 8192);
        cp_commit();
        float4 v0 = *(const float4*)(Bg + (size_t)b_r * HW_DIM + 4 * b_q);
        float4 v1 = *(const float4*)(Bg + (size_t)b_r * HW_DIM + 4 * b_q + 64);
        float* d0 = Bbuf + b_r * B_STRIDE + 4 * b_q;
        d0[0]  = to_tf32(v0.x); d0[1]  = to_tf32(v0.y);
        d0[2]  = to_tf32(v0.z); d0[3]  = to_tf32(v0.w);
        d0[64] = to_tf32(v1.x); d0[65] = to_tf32(v1.y);
        d0[66] = to_tf32(v1.z); d0[67] = to_tf32(v1.w);
        cp_wait_all();
    }
    __syncthreads();

    #pragma unroll 1
    for (int kb = 0; kb < NKB; kb++) {
        const int cur = kb & 1;
        const int nxt = cur ^ 1;
        float4 rb0, rb1;

        if (kb < NKB - 1) {
            const char* Asrc = (const char*)d_Mf + (kb + 1) * 32768;
            #pragma unroll
            for (int pass = 0; pass < 4; pass++)
                cp_async16(as_base + (uint32_t)(nxt * 32768 + tid * 16 + pass * 8192),
                           Asrc + tid * 16 + pass * 8192);
            cp_commit();
            const float* Bsrc = Bg + (size_t)((kb + 1) * KC + b_r) * HW_DIM;
            rb0 = *(const float4*)(Bsrc + 4 * b_q);
            rb1 = *(const float4*)(Bsrc + 4 * b_q + 64);
        }

        // ---- compute on buffer cur ----
        const float* Ac = Abuf + cur * A_WORDS;
        const float* Bc = Bbuf + cur * B_WORDS;
        #pragma unroll
        for (int kk = 0; kk < 4; kk++) {
            const int k0 = kk * 8;
            uint4 a[4];
            #pragma unroll
            for (int mi = 0; mi < 4; mi++) {
                int r16 = wm * 4 + mi;
                a[mi] = *(const uint4*)(Ac + ((r16 * 4 + kk) * 32 + lane) * 4);
            }
            uint32_t bf[4][2];
            #pragma unroll
            for (int ni = 0; ni < 4; ni++) {
                int nn = wn * 32 + ni * 8 + g;
                bf[ni][0] = __float_as_uint(Bc[(k0 + tg) * B_STRIDE + nn]);
                bf[ni][1] = __float_as_uint(Bc[(k0 + tg + 4) * B_STRIDE + nn]);
            }
            #pragma unroll
            for (int mi = 0; mi < 4; mi++)
                #pragma unroll
                for (int ni = 0; ni < 4; ni++)
                    mma_tf32(acc[mi][ni], a[mi].x, a[mi].y, a[mi].z, a[mi].w,
                             bf[ni][0], bf[ni][1]);
        }

        if (kb < NKB - 1) {
            float* d0 = Bbuf + nxt * B_WORDS + b_r * B_STRIDE + 4 * b_q;
            d0[0]  = to_tf32(rb0.x); d0[1]  = to_tf32(rb0.y);
            d0[2]  = to_tf32(rb0.z); d0[3]  = to_tf32(rb0.w);
            d0[64] = to_tf32(rb1.x); d0[65] = to_tf32(rb1.y);
            d0[66] = to_tf32(rb1.z); d0[67] = to_tf32(rb1.w);
            cp_wait_all();
            __syncthreads();
        }
    }

    // ---- epilogue ----
    float* Og = out + (size_t)b * C_DIM * HW_DIM + p0;
    #pragma unroll
    for (int mi = 0; mi < 4; mi++) {
        int c0 = wm * 64 + mi * 16 + g;
        #pragma unroll
        for (int ni = 0; ni < 4; ni++) {
            int p = wn * 32 + ni * 8 + 2 * tg;
            *(float2*)(Og + (size_t)c0 * HW_DIM + p) =
                make_float2(acc[mi][ni][0], acc[mi][ni][1]);
            *(float2*)(Og + (size_t)(c0 + 8) * HW_DIM + p) =
                make_float2(acc[mi][ni][2], acc[mi][ni][3]);
        }
    }
}

// ---------------------------------------------------------------------------
extern "C" void kernel_launch(void* const* d_in, const int* in_sizes, int n_in,
                              void* d_out, int out_size) {
    const float* feat = (const float*)d_in[0];   // [B, C, H, W] fp32
    const float* cb   = (const float*)d_in[1];   // [N, C] fp32
    float* out        = (float*)d_out;           // [B, C, H, W] fp32

    mmat_kernel<<<dim3(16, 16), 256>>>(cb);

    cudaFuncSetAttribute(gemm_kernel,
                         cudaFuncAttributeMaxDynamicSharedMemorySize, SMEM_BYTES);
    gemm_kernel<<<dim3(HW_DIM / N_TILE, BATCH), 512, SMEM_BYTES>>>(feat, out);
}

// round 12
// speedup vs baseline: 1.2509x; 1.2509x over previous
#include <cuda_runtime.h>
#include <cstdint>

#define C_DIM   256
#define NCODES  256
#define HW_DIM  32768       // 128*256
#define BATCH   4
#define M_TILE  128
#define N_TILE  128         // pixels per CTA
#define KC      32          // K-chunk
#define NKB     8           // 256 / 32

// Inverse norms and projection matrix in GEMM *fragment order*:
// d_Mf[ (((kb*16 + r16)*4 + kk)*32 + lane)*4 + comp ]
//   lane = g*4 + tg  (g = m%8 of the 16-row block half, tg = k%4)
//   comp = hm + 2*hk (a0=(m,k), a1=(m+8,k), a2=(m,k+4), a3=(m+8,k+4))
__device__ float d_inv_norm[NCODES];
__device__ float d_Mf[C_DIM * C_DIM];

// ---------------------------------------------------------------------------
// smem sizes (words)
// ---------------------------------------------------------------------------
#define A_WORDS   4096                 // one A stage: 16KB (8 r16 x 4 kk x 32 x 4)
#define BP_STRIDE 258                  // words per pixel-block (256 + 2 pad)
#define B_WORDS   (16 * BP_STRIDE)     // 4128 words
#define SMEM_WORDS (2 * A_WORDS + 2 * B_WORDS)
#define SMEM_BYTES (SMEM_WORDS * 4)    // 65792 B -> 2 CTAs/SM

__device__ __forceinline__ float to_tf32(float x) {
    uint32_t u;
    asm("cvt.rna.tf32.f32 %0, %1;" : "=r"(u) : "f"(x));
    return __uint_as_float(u);
}
__device__ __forceinline__ void mma_tf32(float c[4],
                                         uint32_t a0, uint32_t a1, uint32_t a2, uint32_t a3,
                                         uint32_t b0, uint32_t b1) {
    asm volatile(
        "mma.sync.aligned.m16n8k8.row.col.f32.tf32.tf32.f32 "
        "{%0,%1,%2,%3}, {%4,%5,%6,%7}, {%8,%9}, {%0,%1,%2,%3};"
        : "+f"(c[0]), "+f"(c[1]), "+f"(c[2]), "+f"(c[3])
        : "r"(a0), "r"(a1), "r"(a2), "r"(a3), "r"(b0), "r"(b1));
}
__device__ __forceinline__ void cp_async16(uint32_t smem_addr, const void* g) {
    asm volatile("cp.async.cg.shared.global [%0], [%1], 16;" :: "r"(smem_addr), "l"(g));
}
__device__ __forceinline__ void cp_commit() { asm volatile("cp.async.commit_group;"); }
__device__ __forceinline__ void cp_wait_all() { asm volatile("cp.async.wait_group 0;"); }

// ---------------------------------------------------------------------------
// Kernel 0: inv_norm[n] = 1 / sum_c cb[n][c]^2   (coalesced)
// ---------------------------------------------------------------------------
__global__ void norm_kernel(const float* __restrict__ cb) {
    int n = blockIdx.x;
    int c = threadIdx.x;
    float v = cb[n * C_DIM + c];
    float s = v * v;
    #pragma unroll
    for (int off = 16; off; off >>= 1) s += __shfl_xor_sync(0xffffffffu, s, off);
    __shared__ float ws[8];
    if ((c & 31) == 0) ws[c >> 5] = s;
    __syncthreads();
    if (c < 8) {
        float t = ws[c];
        #pragma unroll
        for (int off = 4; off; off >>= 1) t += __shfl_xor_sync(0xffu, t, off);
        if (c == 0) d_inv_norm[n] = 1.0f / t;
    }
}

// ---------------------------------------------------------------------------
// Kernel 1: M[i][j] = sum_n cb[n][i]*cb[n][j]*inv_norm[n], TF32-rounded,
// written in GEMM fragment order. Grid (16,16) x 256 threads.
// ---------------------------------------------------------------------------
__global__ void mmat_kernel(const float* __restrict__ cb) {
    __shared__ float sI[NCODES][16];
    __shared__ float sJ[NCODES][16];
    const int I0 = blockIdx.x * 16, J0 = blockIdx.y * 16;
    const int tid = threadIdx.x;

    for (int e = tid; e < NCODES * 16; e += 256) {
        int n = e >> 4, ii = e & 15;
        sI[n][ii] = cb[n * C_DIM + I0 + ii];
        sJ[n][ii] = cb[n * C_DIM + J0 + ii] * d_inv_norm[n];
    }
    __syncthreads();

    const int ti = tid & 15, tj = tid >> 4;
    float acc = 0.0f;
    #pragma unroll 8
    for (int n = 0; n < NCODES; n++) acc += sI[n][ti] * sJ[n][tj];

    const int i = I0 + ti, j = J0 + tj;
    const int r16 = i >> 4, g = i & 7, hm = (i >> 3) & 1;
    const int kb = j >> 5, kk = (j >> 3) & 3, tg = j & 3, hk = (j >> 2) & 1;
    const int lane = g * 4 + tg;
    const int comp = hm + 2 * hk;
    d_Mf[(((kb * 16 + r16) * 4 + kk) * 32 + lane) * 4 + comp] = to_tf32(acc);
}

// ---------------------------------------------------------------------------
// Kernel 2: out[b][c][p] = sum_k M[c][k] * feat[b][k][p]
// CTA tile 128(M) x 128(N), 256 threads (2 M-warps x 4 N-warps, 64x32 each),
// K chunks of 32, double-buffered, 2 CTAs/SM.
// Grid (HW/128, 2 M-halves, B).
// ---------------------------------------------------------------------------
__global__ void __launch_bounds__(256, 2)
gemm_kernel(const float* __restrict__ feat, float* __restrict__ out) {
    extern __shared__ float smem[];
    float* const Abuf = smem;                       // 2 x A_WORDS
    float* const Bbuf = smem + 2 * A_WORDS;         // 2 x B_WORDS

    const int tid  = threadIdx.x;
    const int lane = tid & 31;
    const int warp = tid >> 5;
    const int g    = lane >> 2;
    const int tg   = lane & 3;
    const int wm   = warp >> 2;          // 0..1, 64 M-rows each
    const int wn   = warp & 3;           // 0..3, 32 pixels each

    const int p0 = blockIdx.x * N_TILE;
    const int h  = blockIdx.y;           // M-half (0..1)
    const int b  = blockIdx.z;
    const float* Bg = feat + (size_t)b * C_DIM * HW_DIM + p0;

    // B loader mapping: k row = tid>>3 (0..31), px float4 index = tid&7, x4 groups
    const int b_k  = tid >> 3;
    const int b_p4 = tid & 7;
    // precomputed smem word base for this thread's B stores
    const int b_kk   = b_k >> 3;
    const int b_comp = (b_k >> 2) & 1;
    const int b_k2   = b_k & 3;
    const int b_wbase = (b_p4 >> 1) * BP_STRIDE + b_kk * 64 +
                        (b_p4 & 1) * 32 + b_k2 * 2 + b_comp;

    const uint32_t as_base = (uint32_t)__cvta_generic_to_shared(Abuf);

    float acc[4][4][4];
    #pragma unroll
    for (int mi = 0; mi < 4; mi++)
        #pragma unroll
        for (int ni = 0; ni < 4; ni++)
            #pragma unroll
            for (int q = 0; q < 4; q++) acc[mi][ni][q] = 0.0f;

    // ---- prologue: stage 0 ----
    {
        const char* Asrc = (const char*)(d_Mf + (size_t)(0 * 16 + h * 8) * 512);
        #pragma unroll
        for (int pass = 0; pass < 4; pass++)
            cp_async16(as_base + (uint32_t)(tid * 16 + pass * 4096),
                       Asrc + tid * 16 + pass * 4096);
        cp_commit();
        const float* Bsrc = Bg + (size_t)b_k * HW_DIM + 4 * b_p4;
        #pragma unroll
        for (int v = 0; v < 4; v++) {
            float4 vv = *(const float4*)(Bsrc + 32 * v);
            float* d = Bbuf + b_wbase + v * (4 * BP_STRIDE);
            d[0]  = to_tf32(vv.x); d[8]  = to_tf32(vv.y);
            d[16] = to_tf32(vv.z); d[24] = to_tf32(vv.w);
        }
        cp_wait_all();
    }
    __syncthreads();

    #pragma unroll 1
    for (int kb = 0; kb < NKB; kb++) {
        const int cur = kb & 1;
        const int nxt = cur ^ 1;
        float4 rb[4];

        if (kb < NKB - 1) {
            const char* Asrc =
                (const char*)(d_Mf + (size_t)((kb + 1) * 16 + h * 8) * 512);
            #pragma unroll
            for (int pass = 0; pass < 4; pass++)
                cp_async16(as_base + (uint32_t)(nxt * 16384 + tid * 16 + pass * 4096),
                           Asrc + tid * 16 + pass * 4096);
            cp_commit();
            const float* Bsrc = Bg + (size_t)((kb + 1) * KC + b_k) * HW_DIM + 4 * b_p4;
            #pragma unroll
            for (int v = 0; v < 4; v++) rb[v] = *(const float4*)(Bsrc + 32 * v);
        }

        // ---- compute on buffer cur ----
        const float* Ac = Abuf + cur * A_WORDS;
        const float* Bc = Bbuf + cur * B_WORDS;
        #pragma unroll
        for (int kk = 0; kk < 4; kk++) {
            uint4 a[4];
            #pragma unroll
            for (int mi = 0; mi < 4; mi++) {
                int r16l = wm * 4 + mi;
                a[mi] = *(const uint4*)(Ac + ((r16l * 4 + kk) * 32 + lane) * 4);
            }
            uint2 bf[4];
            #pragma unroll
            for (int ni = 0; ni < 4; ni++) {
                int pblk = wn * 4 + ni;
                bf[ni] = *(const uint2*)(Bc + pblk * BP_STRIDE + kk * 64 + lane * 2);
            }
            #pragma unroll
            for (int mi = 0; mi < 4; mi++)
                #pragma unroll
                for (int ni = 0; ni < 4; ni++)
                    mma_tf32(acc[mi][ni], a[mi].x, a[mi].y, a[mi].z, a[mi].w,
                             bf[ni].x, bf[ni].y);
        }

        if (kb < NKB - 1) {
            float* dbase = Bbuf + nxt * B_WORDS + b_wbase;
            #pragma unroll
            for (int v = 0; v < 4; v++) {
                float* d = dbase + v * (4 * BP_STRIDE);
                d[0]  = to_tf32(rb[v].x); d[8]  = to_tf32(rb[v].y);
                d[16] = to_tf32(rb[v].z); d[24] = to_tf32(rb[v].w);
            }
            cp_wait_all();
            __syncthreads();
        }
    }

    // ---- epilogue ----
    float* Og = out + (size_t)b * C_DIM * HW_DIM + (size_t)h * M_TILE * HW_DIM + p0;
    #pragma unroll
    for (int mi = 0; mi < 4; mi++) {
        int c0 = wm * 64 + mi * 16 + g;
        #pragma unroll
        for (int ni = 0; ni < 4; ni++) {
            int p = wn * 32 + ni * 8 + 2 * tg;
            *(float2*)(Og + (size_t)c0 * HW_DIM + p) =
                make_float2(acc[mi][ni][0], acc[mi][ni][1]);
            *(float2*)(Og + (size_t)(c0 + 8) * HW_DIM + p) =
                make_float2(acc[mi][ni][2], acc[mi][ni][3]);
        }
    }
}

// ---------------------------------------------------------------------------
extern "C" void kernel_launch(void* const* d_in, const int* in_sizes, int n_in,
                              void* d_out, int out_size) {
    const float* feat = (const float*)d_in[0];   // [B, C, H, W] fp32
    const float* cb   = (const float*)d_in[1];   // [N, C] fp32
    float* out        = (float*)d_out;           // [B, C, H, W] fp32

    norm_kernel<<<NCODES, C_DIM>>>(cb);
    mmat_kernel<<<dim3(16, 16), 256>>>(cb);

    cudaFuncSetAttribute(gemm_kernel,
                         cudaFuncAttributeMaxDynamicSharedMemorySize, SMEM_BYTES);
    gemm_kernel<<<dim3(HW_DIM / N_TILE, 2, BATCH), 256, SMEM_BYTES>>>(feat, out);
}

// round 13
// speedup vs baseline: 1.4219x; 1.1368x over previous
#include <cuda_runtime.h>
#include <cstdint>

#define C_DIM   256
#define NCODES  256
#define HW_DIM  32768       // 128*256
#define BATCH   4
#define M_TILE  256
#define N_TILE  128         // pixels per CTA
#define KC      32          // K-chunk
#define NKB     8           // 256 / 32
#define NSTAGE  3

// Projection matrix, TF32-rounded (RNA), stored in GEMM *fragment order*:
// d_Mf[ (((kb*16 + r16)*4 + kk)*32 + lane)*4 + comp ]
//   lane = g*4 + tg  (g = m%8 of the 16-row half, tg = k%4)
//   comp = hm + 2*hk (a0=(m,k), a1=(m+8,k), a2=(m,k+4), a3=(m+8,k+4))
__device__ float d_Mf[C_DIM * C_DIM];

// ---------------------------------------------------------------------------
// smem (words): per stage, A (32KB) then B (32 rows x 136 words, padded)
// ---------------------------------------------------------------------------
#define A_WORDS     8192
#define B_STRIDE    136                  // 136 % 32 == 8 -> conflict-free frags
#define B_WORDS     (32 * B_STRIDE)      // 4352 words
#define STAGE_WORDS (A_WORDS + B_WORDS)  // 12544 words = 50176 B
#define SMEM_BYTES  (NSTAGE * STAGE_WORDS * 4)   // 150528 B

__device__ __forceinline__ float to_tf32(float x) {
    uint32_t u;
    asm("cvt.rna.tf32.f32 %0, %1;" : "=r"(u) : "f"(x));
    return __uint_as_float(u);
}
__device__ __forceinline__ void mma_tf32(float c[4],
                                         uint32_t a0, uint32_t a1, uint32_t a2, uint32_t a3,
                                         uint32_t b0, uint32_t b1) {
    asm volatile(
        "mma.sync.aligned.m16n8k8.row.col.f32.tf32.tf32.f32 "
        "{%0,%1,%2,%3}, {%4,%5,%6,%7}, {%8,%9}, {%0,%1,%2,%3};"
        : "+f"(c[0]), "+f"(c[1]), "+f"(c[2]), "+f"(c[3])
        : "r"(a0), "r"(a1), "r"(a2), "r"(a3), "r"(b0), "r"(b1));
}
__device__ __forceinline__ void cp_async16(uint32_t smem_addr, const void* g) {
    asm volatile("cp.async.cg.shared.global [%0], [%1], 16;" :: "r"(smem_addr), "l"(g));
}
__device__ __forceinline__ void cp_commit() { asm volatile("cp.async.commit_group;"); }

// ---------------------------------------------------------------------------
// Kernel 0: fused inverse-norms + M in fragment order. Grid (16,16) x 256.
// Norms computed warp-per-row (coalesced float4 reads).
// ---------------------------------------------------------------------------
__global__ void mmat_kernel(const float* __restrict__ cb) {
    __shared__ float s_inv[NCODES];
    __shared__ float sI[NCODES][16];
    __shared__ float sJ[NCODES][16];
    const int I0 = blockIdx.x * 16, J0 = blockIdx.y * 16;
    const int tid = threadIdx.x, lane = tid & 31, warp = tid >> 5;

    // warp-per-row norms: warp w handles rows w, w+8, ...
    for (int r = warp; r < NCODES; r += 8) {
        const float4* row = (const float4*)(cb + r * C_DIM);
        float4 v0 = row[lane];
        float4 v1 = row[lane + 32];
        float s = v0.x * v0.x + v0.y * v0.y + v0.z * v0.z + v0.w * v0.w
                + v1.x * v1.x + v1.y * v1.y + v1.z * v1.z + v1.w * v1.w;
        #pragma unroll
        for (int off = 16; off; off >>= 1) s += __shfl_xor_sync(0xffffffffu, s, off);
        if (lane == 0) s_inv[r] = 1.0f / s;
    }
    __syncthreads();

    for (int e = tid; e < NCODES * 16; e += 256) {
        int n = e >> 4, ii = e & 15;
        sI[n][ii] = cb[n * C_DIM + I0 + ii];
        sJ[n][ii] = cb[n * C_DIM + J0 + ii] * s_inv[n];
    }
    __syncthreads();

    const int ti = tid & 15, tj = tid >> 4;
    float acc = 0.0f;
    #pragma unroll 8
    for (int n = 0; n < NCODES; n++) acc += sI[n][ti] * sJ[n][tj];

    const int i = I0 + ti, j = J0 + tj;
    const int r16 = i >> 4, g = i & 7, hm = (i >> 3) & 1;
    const int kb = j >> 5, kk = (j >> 3) & 3, tg = j & 3, hk = (j >> 2) & 1;
    d_Mf[(((kb * 16 + r16) * 4 + kk) * 32 + (g * 4 + tg)) * 4 + (hm + 2 * hk)] =
        to_tf32(acc);
}

// ---------------------------------------------------------------------------
// Kernel 1: out[b][c][p] = sum_k M[c][k] * feat[b][k][p]
// CTA tile 256(M) x 128(N), 512 threads (4 M-warps x 4 N-warps, 64x32 each),
// 3-stage cp.async ring, B consumed fp32 (HW tf32 truncation in HMMA).
// ---------------------------------------------------------------------------
__global__ void __launch_bounds__(512)
gemm_kernel(const float* __restrict__ feat, float* __restrict__ out) {
    extern __shared__ float smem[];

    const int tid  = threadIdx.x;
    const int lane = tid & 31;
    const int warp = tid >> 5;
    const int g    = lane >> 2;
    const int tg   = lane & 3;
    const int wm   = warp >> 2;          // 0..3, 64 M-rows each
    const int wn   = warp & 3;           // 0..3, 32 pixels each

    const int p0 = blockIdx.x * N_TILE;
    const int b  = blockIdx.y;
    const float* Bg = feat + (size_t)b * C_DIM * HW_DIM + p0;

    // B loader: 2 x 16B per thread; idx = tid + 512*i -> row = idx>>5, seg = idx&31
    const int b_row0 = tid >> 5;          // rows 0..15  (i=0)
    const int b_seg  = tid & 31;          //            (i=1 adds +16 rows)

    const uint32_t sm_base = (uint32_t)__cvta_generic_to_shared(smem);

    float acc[4][4][4];
    #pragma unroll
    for (int mi = 0; mi < 4; mi++)
        #pragma unroll
        for (int ni = 0; ni < 4; ni++)
            #pragma unroll
            for (int q = 0; q < 4; q++) acc[mi][ni][q] = 0.0f;

    // ---- stage issue helper (A: 4x16B, B: 2x16B per thread) ----
    auto issue = [&](int kb, int s) {
        const uint32_t a_dst = sm_base + (uint32_t)(s * STAGE_WORDS * 4);
        const char* Asrc = (const char*)(d_Mf + (size_t)kb * A_WORDS);
        #pragma unroll
        for (int pass = 0; pass < 4; pass++)
            cp_async16(a_dst + (uint32_t)(tid * 16 + pass * 8192),
                       Asrc + tid * 16 + pass * 8192);
        const uint32_t b_dst = a_dst + A_WORDS * 4;
        #pragma unroll
        for (int i = 0; i < 2; i++) {
            int row = b_row0 + i * 16;
            cp_async16(b_dst + (uint32_t)(row * (B_STRIDE * 4) + b_seg * 16),
                       Bg + (size_t)(kb * KC + row) * HW_DIM + b_seg * 4);
        }
        cp_commit();
    };

    issue(0, 0);
    issue(1, 1);

    #pragma unroll 1
    for (int kb = 0; kb < NKB; kb++) {
        const int s = kb % NSTAGE;

        if (kb == NKB - 1) asm volatile("cp.async.wait_group 0;");
        else               asm volatile("cp.async.wait_group 1;");
        __syncthreads();
        if (kb + 2 < NKB) issue(kb + 2, (kb + 2) % NSTAGE);

        const float* Ac = smem + s * STAGE_WORDS;
        const float* Bc = Ac + A_WORDS;
        #pragma unroll
        for (int kk = 0; kk < 4; kk++) {
            uint4 a[4];
            #pragma unroll
            for (int mi = 0; mi < 4; mi++)
                a[mi] = *(const uint4*)(Ac + (((wm * 4 + mi) * 4 + kk) * 32 + lane) * 4);
            uint32_t bf[4][2];
            #pragma unroll
            for (int ni = 0; ni < 4; ni++) {
                int nn = wn * 32 + ni * 8 + g;
                bf[ni][0] = __float_as_uint(Bc[(kk * 8 + tg) * B_STRIDE + nn]);
                bf[ni][1] = __float_as_uint(Bc[(kk * 8 + tg + 4) * B_STRIDE + nn]);
            }
            #pragma unroll
            for (int mi = 0; mi < 4; mi++)
                #pragma unroll
                for (int ni = 0; ni < 4; ni++)
                    mma_tf32(acc[mi][ni], a[mi].x, a[mi].y, a[mi].z, a[mi].w,
                             bf[ni][0], bf[ni][1]);
        }
    }

    // ---- epilogue ----
    float* Og = out + (size_t)b * C_DIM * HW_DIM + p0;
    #pragma unroll
    for (int mi = 0; mi < 4; mi++) {
        int c0 = wm * 64 + mi * 16 + g;
        #pragma unroll
        for (int ni = 0; ni < 4; ni++) {
            int p = wn * 32 + ni * 8 + 2 * tg;
            *(float2*)(Og + (size_t)c0 * HW_DIM + p) =
                make_float2(acc[mi][ni][0], acc[mi][ni][1]);
            *(float2*)(Og + (size_t)(c0 + 8) * HW_DIM + p) =
                make_float2(acc[mi][ni][2], acc[mi][ni][3]);
        }
    }
}

// ---------------------------------------------------------------------------
extern "C" void kernel_launch(void* const* d_in, const int* in_sizes, int n_in,
                              void* d_out, int out_size) {
    const float* feat = (const float*)d_in[0];   // [B, C, H, W] fp32
    const float* cb   = (const float*)d_in[1];   // [N, C] fp32
    float* out        = (float*)d_out;           // [B, C, H, W] fp32

    mmat_kernel<<<dim3(16, 16), 256>>>(cb);

    cudaFuncSetAttribute(gemm_kernel,
                         cudaFuncAttributeMaxDynamicSharedMemorySize, SMEM_BYTES);
    gemm_kernel<<<dim3(HW_DIM / N_TILE, BATCH), 512, SMEM_BYTES>>>(feat, out);
}

// round 14
// speedup vs baseline: 1.6103x; 1.1325x over previous
#include <cuda_runtime.h>
#include <cstdint>

#define C_DIM   256
#define NCODES  256
#define HW_DIM  32768       // 128*256
#define BATCH   4
#define M_TILE  256
#define N_TILE  128         // pixels per CTA
#define KC      32          // K-chunk
#define NKB     8           // 256 / 32
#define NSTAGE  3

// Inverse norms + projection matrix, TF32-rounded (RNA), in GEMM *fragment order*:
// d_Mf[ (((kb*16 + r16)*4 + kk)*32 + lane)*4 + comp ]
//   lane = g*4 + tg  (g = m%8 of the 16-row half, tg = k%4)
//   comp = hm + 2*hk (a0=(m,k), a1=(m+8,k), a2=(m,k+4), a3=(m+8,k+4))
__device__ float d_inv_norm[NCODES];
__device__ float d_Mf[C_DIM * C_DIM];

// ---------------------------------------------------------------------------
// smem (words): per stage, A (32KB) then B (32 rows x 136 words, padded)
// ---------------------------------------------------------------------------
#define A_WORDS     8192
#define B_STRIDE    136                  // 136 % 32 == 8 -> conflict-free frags
#define B_WORDS     (32 * B_STRIDE)      // 4352 words
#define STAGE_WORDS (A_WORDS + B_WORDS)  // 12544 words = 50176 B
#define SMEM_BYTES  (NSTAGE * STAGE_WORDS * 4)   // 150528 B

__device__ __forceinline__ float to_tf32(float x) {
    uint32_t u;
    asm("cvt.rna.tf32.f32 %0, %1;" : "=r"(u) : "f"(x));
    return __uint_as_float(u);
}
__device__ __forceinline__ void mma_tf32(float c[4],
                                         uint32_t a0, uint32_t a1, uint32_t a2, uint32_t a3,
                                         uint32_t b0, uint32_t b1) {
    asm volatile(
        "mma.sync.aligned.m16n8k8.row.col.f32.tf32.tf32.f32 "
        "{%0,%1,%2,%3}, {%4,%5,%6,%7}, {%8,%9}, {%0,%1,%2,%3};"
        : "+f"(c[0]), "+f"(c[1]), "+f"(c[2]), "+f"(c[3])
        : "r"(a0), "r"(a1), "r"(a2), "r"(a3), "r"(b0), "r"(b1));
}
__device__ __forceinline__ void cp_async16(uint32_t smem_addr, const void* g) {
    asm volatile("cp.async.cg.shared.global [%0], [%1], 16;" :: "r"(smem_addr), "l"(g));
}
__device__ __forceinline__ void cp_commit() { asm volatile("cp.async.commit_group;"); }

// ---------------------------------------------------------------------------
// Kernel 0: inv_norm[n] = 1 / sum_c cb[n][c]^2   (coalesced, one block/row)
// ---------------------------------------------------------------------------
__global__ void norm_kernel(const float* __restrict__ cb) {
    int n = blockIdx.x;
    int c = threadIdx.x;
    float v = cb[n * C_DIM + c];
    float s = v * v;
    #pragma unroll
    for (int off = 16; off; off >>= 1) s += __shfl_xor_sync(0xffffffffu, s, off);
    __shared__ float ws[8];
    if ((c & 31) == 0) ws[c >> 5] = s;
    __syncthreads();
    if (c < 8) {
        float t = ws[c];
        #pragma unroll
        for (int off = 4; off; off >>= 1) t += __shfl_xor_sync(0xffu, t, off);
        if (c == 0) d_inv_norm[n] = 1.0f / t;
    }
}

// ---------------------------------------------------------------------------
// Kernel 1: M[i][j] = sum_n cb[n][i]*cb[n][j]*inv_norm[n], TF32-rounded,
// written in GEMM fragment order. Grid (16,16) x 256 threads.
// ---------------------------------------------------------------------------
__global__ void mmat_kernel(const float* __restrict__ cb) {
    __shared__ float sI[NCODES][16];
    __shared__ float sJ[NCODES][16];
    const int I0 = blockIdx.x * 16, J0 = blockIdx.y * 16;
    const int tid = threadIdx.x;

    for (int e = tid; e < NCODES * 16; e += 256) {
        int n = e >> 4, ii = e & 15;
        sI[n][ii] = cb[n * C_DIM + I0 + ii];
        sJ[n][ii] = cb[n * C_DIM + J0 + ii] * d_inv_norm[n];
    }
    __syncthreads();

    const int ti = tid & 15, tj = tid >> 4;
    float acc = 0.0f;
    #pragma unroll 8
    for (int n = 0; n < NCODES; n++) acc += sI[n][ti] * sJ[n][tj];

    const int i = I0 + ti, j = J0 + tj;
    const int r16 = i >> 4, g = i & 7, hm = (i >> 3) & 1;
    const int kb = j >> 5, kk = (j >> 3) & 3, tg = j & 3, hk = (j >> 2) & 1;
    d_Mf[(((kb * 16 + r16) * 4 + kk) * 32 + (g * 4 + tg)) * 4 + (hm + 2 * hk)] =
        to_tf32(acc);
}

// ---------------------------------------------------------------------------
// Kernel 2: out[b][c][p] = sum_k M[c][k] * feat[b][k][p]
// CTA tile 256(M) x 128(N), 512 threads (4 M-warps x 4 N-warps, 64x32 each),
// 3-stage cp.async ring, B consumed fp32 (HW tf32 truncation in HMMA).
// ---------------------------------------------------------------------------
__global__ void __launch_bounds__(512)
gemm_kernel(const float* __restrict__ feat, float* __restrict__ out) {
    extern __shared__ float smem[];

    const int tid  = threadIdx.x;
    const int lane = tid & 31;
    const int warp = tid >> 5;
    const int g    = lane >> 2;
    const int tg   = lane & 3;
    const int wm   = warp >> 2;          // 0..3, 64 M-rows each
    const int wn   = warp & 3;           // 0..3, 32 pixels each

    const int p0 = blockIdx.x * N_TILE;
    const int b  = blockIdx.y;
    const float* Bg = feat + (size_t)b * C_DIM * HW_DIM + p0;

    // B loader: 2 x 16B per thread
    const int b_row0 = tid >> 5;          // rows 0..15  (second pass +16)
    const int b_seg  = tid & 31;

    const uint32_t sm_base = (uint32_t)__cvta_generic_to_shared(smem);

    float acc[4][4][4];
    #pragma unroll
    for (int mi = 0; mi < 4; mi++)
        #pragma unroll
        for (int ni = 0; ni < 4; ni++)
            #pragma unroll
            for (int q = 0; q < 4; q++) acc[mi][ni][q] = 0.0f;

    // ---- stage issue helper (A: 4x16B, B: 2x16B per thread) ----
    auto issue = [&](int kb, int s) {
        const uint32_t a_dst = sm_base + (uint32_t)(s * STAGE_WORDS * 4);
        const char* Asrc = (const char*)(d_Mf + (size_t)kb * A_WORDS);
        #pragma unroll
        for (int pass = 0; pass < 4; pass++)
            cp_async16(a_dst + (uint32_t)(tid * 16 + pass * 8192),
                       Asrc + tid * 16 + pass * 8192);
        const uint32_t b_dst = a_dst + A_WORDS * 4;
        #pragma unroll
        for (int i = 0; i < 2; i++) {
            int row = b_row0 + i * 16;
            cp_async16(b_dst + (uint32_t)(row * (B_STRIDE * 4) + b_seg * 16),
                       Bg + (size_t)(kb * KC + row) * HW_DIM + b_seg * 4);
        }
        cp_commit();
    };

    issue(0, 0);
    issue(1, 1);

    #pragma unroll 1
    for (int kb = 0; kb < NKB; kb++) {
        const int s = kb % NSTAGE;

        if (kb == NKB - 1) asm volatile("cp.async.wait_group 0;");
        else               asm volatile("cp.async.wait_group 1;");
        __syncthreads();
        if (kb + 2 < NKB) issue(kb + 2, (kb + 2) % NSTAGE);

        const float* Ac = smem + s * STAGE_WORDS;
        const float* Bc = Ac + A_WORDS;
        #pragma unroll
        for (int kk = 0; kk < 4; kk++) {
            uint4 a[4];
            #pragma unroll
            for (int mi = 0; mi < 4; mi++)
                a[mi] = *(const uint4*)(Ac + (((wm * 4 + mi) * 4 + kk) * 32 + lane) * 4);
            uint32_t bf[4][2];
            #pragma unroll
            for (int ni = 0; ni < 4; ni++) {
                int nn = wn * 32 + ni * 8 + g;
                bf[ni][0] = __float_as_uint(Bc[(kk * 8 + tg) * B_STRIDE + nn]);
                bf[ni][1] = __float_as_uint(Bc[(kk * 8 + tg + 4) * B_STRIDE + nn]);
            }
            #pragma unroll
            for (int mi = 0; mi < 4; mi++)
                #pragma unroll
                for (int ni = 0; ni < 4; ni++)
                    mma_tf32(acc[mi][ni], a[mi].x, a[mi].y, a[mi].z, a[mi].w,
                             bf[ni][0], bf[ni][1]);
        }
    }

    // ---- epilogue ----
    float* Og = out + (size_t)b * C_DIM * HW_DIM + p0;
    #pragma unroll
    for (int mi = 0; mi < 4; mi++) {
        int c0 = wm * 64 + mi * 16 + g;
        #pragma unroll
        for (int ni = 0; ni < 4; ni++) {
            int p = wn * 32 + ni * 8 + 2 * tg;
            *(float2*)(Og + (size_t)c0 * HW_DIM + p) =
                make_float2(acc[mi][ni][0], acc[mi][ni][1]);
            *(float2*)(Og + (size_t)(c0 + 8) * HW_DIM + p) =
                make_float2(acc[mi][ni][2], acc[mi][ni][3]);
        }
    }
}

// ---------------------------------------------------------------------------
extern "C" void kernel_launch(void* const* d_in, const int* in_sizes, int n_in,
                              void* d_out, int out_size) {
    const float* feat = (const float*)d_in[0];   // [B, C, H, W] fp32
    const float* cb   = (const float*)d_in[1];   // [N, C] fp32
    float* out        = (float*)d_out;           // [B, C, H, W] fp32

    norm_kernel<<<NCODES, C_DIM>>>(cb);
    mmat_kernel<<<dim3(16, 16), 256>>>(cb);

    cudaFuncSetAttribute(gemm_kernel,
                         cudaFuncAttributeMaxDynamicSharedMemorySize, SMEM_BYTES);
    gemm_kernel<<<dim3(HW_DIM / N_TILE, BATCH), 512, SMEM_BYTES>>>(feat, out);
}

// round 15
// speedup vs baseline: 1.6766x; 1.0412x over previous
#include <cuda_runtime.h>
#include <cstdint>

#define C_DIM   256
#define NCODES  256
#define HW_DIM  32768       // 128*256
#define BATCH   4
#define M_TILE  128
#define N_TILE  128         // pixels per CTA
#define KC      32          // K-chunk
#define NKB     8           // 256 / 32
#define NSTAGE  3

// Inverse norms + projection matrix, TF32-rounded (RNA), in GEMM *fragment order*:
// d_Mf[ (((kb*16 + r16)*4 + kk)*32 + lane)*4 + comp ]
//   lane = g*4 + tg  (g = m%8 of the 16-row half, tg = k%4)
//   comp = hm + 2*hk (a0=(m,k), a1=(m+8,k), a2=(m,k+4), a3=(m+8,k+4))
__device__ float d_inv_norm[NCODES];
__device__ float d_Mf[C_DIM * C_DIM];

// ---------------------------------------------------------------------------
// smem (words): per stage, A (16KB: 8 r16-blocks) then B (32 rows x 136 words)
// ---------------------------------------------------------------------------
#define A_WORDS     4096
#define B_STRIDE    136                  // 136 % 32 == 8 -> conflict-free frags
#define B_WORDS     (32 * B_STRIDE)      // 4352 words
#define STAGE_WORDS (A_WORDS + B_WORDS)  // 8448 words = 33792 B
#define SMEM_BYTES  (NSTAGE * STAGE_WORDS * 4)   // 101376 B -> 2 CTAs/SM

__device__ __forceinline__ float to_tf32(float x) {
    uint32_t u;
    asm("cvt.rna.tf32.f32 %0, %1;" : "=r"(u) : "f"(x));
    return __uint_as_float(u);
}
__device__ __forceinline__ void mma_tf32(float c[4],
                                         uint32_t a0, uint32_t a1, uint32_t a2, uint32_t a3,
                                         uint32_t b0, uint32_t b1) {
    asm volatile(
        "mma.sync.aligned.m16n8k8.row.col.f32.tf32.tf32.f32 "
        "{%0,%1,%2,%3}, {%4,%5,%6,%7}, {%8,%9}, {%0,%1,%2,%3};"
        : "+f"(c[0]), "+f"(c[1]), "+f"(c[2]), "+f"(c[3])
        : "r"(a0), "r"(a1), "r"(a2), "r"(a3), "r"(b0), "r"(b1));
}
__device__ __forceinline__ void cp_async16(uint32_t smem_addr, const void* g) {
    asm volatile("cp.async.cg.shared.global [%0], [%1], 16;" :: "r"(smem_addr), "l"(g));
}
__device__ __forceinline__ void cp_commit() { asm volatile("cp.async.commit_group;"); }

// ---------------------------------------------------------------------------
// Kernel 0: inv_norm[n] = 1 / sum_c cb[n][c]^2   (coalesced, one block/row)
// ---------------------------------------------------------------------------
__global__ void norm_kernel(const float* __restrict__ cb) {
    int n = blockIdx.x;
    int c = threadIdx.x;
    float v = cb[n * C_DIM + c];
    float s = v * v;
    #pragma unroll
    for (int off = 16; off; off >>= 1) s += __shfl_xor_sync(0xffffffffu, s, off);
    __shared__ float ws[8];
    if ((c & 31) == 0) ws[c >> 5] = s;
    __syncthreads();
    if (c < 8) {
        float t = ws[c];
        #pragma unroll
        for (int off = 4; off; off >>= 1) t += __shfl_xor_sync(0xffu, t, off);
        if (c == 0) d_inv_norm[n] = 1.0f / t;
    }
}

// ---------------------------------------------------------------------------
// Kernel 1: M[i][j] = sum_n cb[n][i]*cb[n][j]*inv_norm[n], TF32-rounded,
// written in GEMM fragment order. Grid (16,16) x 256 threads.
// ---------------------------------------------------------------------------
__global__ void mmat_kernel(const float* __restrict__ cb) {
    __shared__ float sI[NCODES][16];
    __shared__ float sJ[NCODES][16];
    const int I0 = blockIdx.x * 16, J0 = blockIdx.y * 16;
    const int tid = threadIdx.x;

    for (int e = tid; e < NCODES * 16; e += 256) {
        int n = e >> 4, ii = e & 15;
        sI[n][ii] = cb[n * C_DIM + I0 + ii];
        sJ[n][ii] = cb[n * C_DIM + J0 + ii] * d_inv_norm[n];
    }
    __syncthreads();

    const int ti = tid & 15, tj = tid >> 4;
    float acc = 0.0f;
    #pragma unroll 8
    for (int n = 0; n < NCODES; n++) acc += sI[n][ti] * sJ[n][tj];

    const int i = I0 + ti, j = J0 + tj;
    const int r16 = i >> 4, g = i & 7, hm = (i >> 3) & 1;
    const int kb = j >> 5, kk = (j >> 3) & 3, tg = j & 3, hk = (j >> 2) & 1;
    d_Mf[(((kb * 16 + r16) * 4 + kk) * 32 + (g * 4 + tg)) * 4 + (hm + 2 * hk)] =
        to_tf32(acc);
}

// ---------------------------------------------------------------------------
// Kernel 2: out[b][c][p] = sum_k M[c][k] * feat[b][k][p]
// CTA tile 128(M) x 128(N), 256 threads (2 M-warps x 4 N-warps, 64x32 each),
// 3-stage cp.async ring, B consumed fp32 (HW tf32 truncation in HMMA).
// Grid (2 M-halves, HW/128, B): halves of the same pixel tile are ADJACENT
// bids -> adjacent SMs, same wave -> second B read served from L2.
// 2 CTAs per SM: one CTA's MMAs cover the other's sync/prefetch bubbles.
// ---------------------------------------------------------------------------
__global__ void __launch_bounds__(256, 2)
gemm_kernel(const float* __restrict__ feat, float* __restrict__ out) {
    extern __shared__ float smem[];

    const int tid  = threadIdx.x;
    const int lane = tid & 31;
    const int warp = tid >> 5;
    const int g    = lane >> 2;
    const int tg   = lane & 3;
    const int wm   = warp >> 2;          // 0..1, 64 M-rows each
    const int wn   = warp & 3;           // 0..3, 32 pixels each

    const int h  = blockIdx.x;           // M-half (0..1)
    const int p0 = blockIdx.y * N_TILE;
    const int b  = blockIdx.z;
    const float* Bg = feat + (size_t)b * C_DIM * HW_DIM + p0;

    const uint32_t sm_base = (uint32_t)__cvta_generic_to_shared(smem);

    float acc[4][4][4];
    #pragma unroll
    for (int mi = 0; mi < 4; mi++)
        #pragma unroll
        for (int ni = 0; ni < 4; ni++)
            #pragma unroll
            for (int q = 0; q < 4; q++) acc[mi][ni][q] = 0.0f;

    // ---- stage issue helper (A: 4x16B, B: 4x16B per thread) ----
    const int b_row0 = tid >> 5;          // B rows 0..7 (+8 per pass)
    const int b_seg  = tid & 31;          // 16B segment within 128-px row
    auto issue = [&](int kb, int s) {
        const uint32_t a_dst = sm_base + (uint32_t)(s * STAGE_WORDS * 4);
        const char* Asrc = (const char*)(d_Mf + (size_t)(kb * 16 + h * 8) * 512);
        #pragma unroll
        for (int pass = 0; pass < 4; pass++)
            cp_async16(a_dst + (uint32_t)(tid * 16 + pass * 4096),
                       Asrc + tid * 16 + pass * 4096);
        const uint32_t b_dst = a_dst + A_WORDS * 4;
        #pragma unroll
        for (int i = 0; i < 4; i++) {
            int row = b_row0 + i * 8;
            cp_async16(b_dst + (uint32_t)(row * (B_STRIDE * 4) + b_seg * 16),
                       Bg + (size_t)(kb * KC + row) * HW_DIM + b_seg * 4);
        }
        cp_commit();
    };

    issue(0, 0);
    issue(1, 1);

    #pragma unroll 1
    for (int kb = 0; kb < NKB; kb++) {
        const int s = kb % NSTAGE;

        if (kb == NKB - 1) asm volatile("cp.async.wait_group 0;");
        else               asm volatile("cp.async.wait_group 1;");
        __syncthreads();
        if (kb + 2 < NKB) issue(kb + 2, (kb + 2) % NSTAGE);

        const float* Ac = smem + s * STAGE_WORDS;
        const float* Bc = Ac + A_WORDS;
        #pragma unroll
        for (int kk = 0; kk < 4; kk++) {
            uint4 a[4];
            #pragma unroll
            for (int mi = 0; mi < 4; mi++)
                a[mi] = *(const uint4*)(Ac + (((wm * 4 + mi) * 4 + kk) * 32 + lane) * 4);
            uint32_t bf[4][2];
            #pragma unroll
            for (int ni = 0; ni < 4; ni++) {
                int nn = wn * 32 + ni * 8 + g;
                bf[ni][0] = __float_as_uint(Bc[(kk * 8 + tg) * B_STRIDE + nn]);
                bf[ni][1] = __float_as_uint(Bc[(kk * 8 + tg + 4) * B_STRIDE + nn]);
            }
            #pragma unroll
            for (int mi = 0; mi < 4; mi++)
                #pragma unroll
                for (int ni = 0; ni < 4; ni++)
                    mma_tf32(acc[mi][ni], a[mi].x, a[mi].y, a[mi].z, a[mi].w,
                             bf[ni][0], bf[ni][1]);
        }
    }

    // ---- epilogue ----
    float* Og = out + (size_t)b * C_DIM * HW_DIM + (size_t)(h * M_TILE) * HW_DIM + p0;
    #pragma unroll
    for (int mi = 0; mi < 4; mi++) {
        int c0 = wm * 64 + mi * 16 + g;
        #pragma unroll
        for (int ni = 0; ni < 4; ni++) {
            int p = wn * 32 + ni * 8 + 2 * tg;
            *(float2*)(Og + (size_t)c0 * HW_DIM + p) =
                make_float2(acc[mi][ni][0], acc[mi][ni][1]);
            *(float2*)(Og + (size_t)(c0 + 8) * HW_DIM + p) =
                make_float2(acc[mi][ni][2], acc[mi][ni][3]);
        }
    }
}

// ---------------------------------------------------------------------------
extern "C" void kernel_launch(void* const* d_in, const int* in_sizes, int n_in,
                              void* d_out, int out_size) {
    const float* feat = (const float*)d_in[0];   // [B, C, H, W] fp32
    const float* cb   = (const float*)d_in[1];   // [N, C] fp32
    float* out        = (float*)d_out;           // [B, C, H, W] fp32

    norm_kernel<<<NCODES, C_DIM>>>(cb);
    mmat_kernel<<<dim3(16, 16), 256>>>(cb);

    cudaFuncSetAttribute(gemm_kernel,
                         cudaFuncAttributeMaxDynamicSharedMemorySize, SMEM_BYTES);
    gemm_kernel<<<dim3(2, HW_DIM / N_TILE, BATCH), 256, SMEM_BYTES>>>(feat, out);
}

// round 16
// speedup vs baseline: 2.1581x; 1.2871x over previous
#include <cuda_runtime.h>
#include <cuda_fp16.h>
#include <cstdint>

#define C_DIM   256
#define NCODES  256
#define HW_DIM  32768       // 128*256
#define BATCH   4
#define M_TILE  128
#define N_TILE  128         // pixels per CTA
#define KC      32          // K-chunk
#define NKB     8           // 256 / 32

// Inverse norms; projection matrix as fp16 in m16n8k16 *fragment order*:
// d_Mfh[ ((((kb*2 + h)*8 + r16)*2 + ks)*32 + lane)*8 + comp*2 + lo ]
//   kb = K-chunk (32), h = M-half (128), r16 = m16 block in half, ks = k16 step
//   lane = g*4 + tg;  comp = hm + 2*hk  (a0..a3);  lo = k parity within pair
__device__ float  d_inv_norm[NCODES];
__device__ __half d_Mfh[C_DIM * C_DIM];

// ---------------------------------------------------------------------------
// smem layout (bytes): 3 A stages of 8192, then 2 B stages of 8704
// B stage: 32 k-rows x 128 px fp16, row pitch 272B (17x16B -> LDSM conflict-free)
// ---------------------------------------------------------------------------
#define A_STAGE    8192
#define B_OFF      (3 * A_STAGE)         // 24576
#define B_PITCH    272
#define B_STAGE    (32 * B_PITCH)        // 8704
#define SMEM_BYTES (B_OFF + 2 * B_STAGE) // 41984 -> 2 CTAs/SM easily

__device__ __forceinline__ void mma_f16(float c[4],
                                        uint32_t a0, uint32_t a1, uint32_t a2, uint32_t a3,
                                        uint32_t b0, uint32_t b1) {
    asm volatile(
        "mma.sync.aligned.m16n8k16.row.col.f32.f16.f16.f32 "
        "{%0,%1,%2,%3}, {%4,%5,%6,%7}, {%8,%9}, {%0,%1,%2,%3};"
        : "+f"(c[0]), "+f"(c[1]), "+f"(c[2]), "+f"(c[3])
        : "r"(a0), "r"(a1), "r"(a2), "r"(a3), "r"(b0), "r"(b1));
}
__device__ __forceinline__ void ldsm_x4_t(uint32_t& r0, uint32_t& r1,
                                          uint32_t& r2, uint32_t& r3, uint32_t addr) {
    asm volatile("ldmatrix.sync.aligned.m8n8.x4.trans.shared.b16 {%0,%1,%2,%3}, [%4];"
                 : "=r"(r0), "=r"(r1), "=r"(r2), "=r"(r3) : "r"(addr));
}
__device__ __forceinline__ void cp_async16(uint32_t smem_addr, const void* g) {
    asm volatile("cp.async.cg.shared.global [%0], [%1], 16;" :: "r"(smem_addr), "l"(g));
}
__device__ __forceinline__ void cp_commit() { asm volatile("cp.async.commit_group;"); }
__device__ __forceinline__ uint32_t h2pack(float x, float y) {
    __half2 h = __float22half2_rn(make_float2(x, y));
    return *(uint32_t*)&h;
}

// ---------------------------------------------------------------------------
// Kernel 0: inv_norm[n] = 1 / sum_c cb[n][c]^2   (coalesced, one block/row)
// ---------------------------------------------------------------------------
__global__ void norm_kernel(const float* __restrict__ cb) {
    int n = blockIdx.x;
    int c = threadIdx.x;
    float v = cb[n * C_DIM + c];
    float s = v * v;
    #pragma unroll
    for (int off = 16; off; off >>= 1) s += __shfl_xor_sync(0xffffffffu, s, off);
    __shared__ float ws[8];
    if ((c & 31) == 0) ws[c >> 5] = s;
    __syncthreads();
    if (c < 8) {
        float t = ws[c];
        #pragma unroll
        for (int off = 4; off; off >>= 1) t += __shfl_xor_sync(0xffu, t, off);
        if (c == 0) d_inv_norm[n] = 1.0f / t;
    }
}

// ---------------------------------------------------------------------------
// Kernel 1: M[i][j] = sum_n cb[n][i]*cb[n][j]*inv_norm[n], RN-rounded fp16,
// written in m16n8k16 fragment order. Grid (16,16) x 256 threads.
// ---------------------------------------------------------------------------
__global__ void mmat_kernel(const float* __restrict__ cb) {
    __shared__ float sI[NCODES][16];
    __shared__ float sJ[NCODES][16];
    const int I0 = blockIdx.x * 16, J0 = blockIdx.y * 16;
    const int tid = threadIdx.x;

    for (int e = tid; e < NCODES * 16; e += 256) {
        int n = e >> 4, ii = e & 15;
        sI[n][ii] = cb[n * C_DIM + I0 + ii];
        sJ[n][ii] = cb[n * C_DIM + J0 + ii] * d_inv_norm[n];
    }
    __syncthreads();

    const int ti = tid & 15, tj = tid >> 4;
    float acc = 0.0f;
    #pragma unroll 8
    for (int n = 0; n < NCODES; n++) acc += sI[n][ti] * sJ[n][tj];

    const int i = I0 + ti, j = J0 + tj;
    const int h = i >> 7, r16 = (i >> 4) & 7, g = i & 7, hm = (i >> 3) & 1;
    const int kb = j >> 5, ks = (j >> 4) & 1;
    const int jj = j & 15, hk = jj >> 3, tg = (jj >> 1) & 3, lo = jj & 1;
    const int lane = g * 4 + tg;
    const int comp = hm + 2 * hk;
    d_Mfh[(((((kb * 2 + h) * 8 + r16) * 2 + ks) * 32 + lane) * 8) + comp * 2 + lo] =
        __float2half_rn(acc);
}

// ---------------------------------------------------------------------------
// Kernel 2: out[b][c][p] = sum_k M[c][k] * feat[b][k][p]
// CTA 128(M) x 128(N), 256 threads (2 M-warps x 4 N-warps, 64x32 each).
// fp16 m16n8k16 MMAs; A via contiguous cp.async (fragment order, 3-stage);
// B: LDG.128 fp32 -> cvt.rn fp16 -> STS.64, consumed via ldmatrix.x4.trans
// (double-buffered). Grid (2 M-halves adjacent, HW/128, B); 2 CTAs/SM.
// ---------------------------------------------------------------------------
__global__ void __launch_bounds__(256, 2)
gemm_kernel(const float* __restrict__ feat, float* __restrict__ out) {
    extern __shared__ char smem[];
    const uint32_t sm_base = (uint32_t)__cvta_generic_to_shared(smem);

    const int tid  = threadIdx.x;
    const int lane = tid & 31;
    const int warp = tid >> 5;
    const int g    = lane >> 2;
    const int tg   = lane & 3;
    const int wm   = warp >> 2;          // 0..1, 64 M-rows each
    const int wn   = warp & 3;           // 0..3, 32 pixels each

    const int h  = blockIdx.x;           // M-half
    const int p0 = blockIdx.y * N_TILE;
    const int b  = blockIdx.z;
    const float* Bg = feat + (size_t)b * C_DIM * HW_DIM + p0;

    // A stage issue: 2 x 16B per thread (8KB stage, contiguous in gmem)
    auto issueA = [&](int kb, int s) {
        const char* src = (const char*)(d_Mfh + (size_t)(kb * 2 + h) * 4096);
        const uint32_t dst = sm_base + (uint32_t)(s * A_STAGE);
        cp_async16(dst + tid * 16, src + tid * 16);
        cp_async16(dst + 4096 + tid * 16, src + 4096 + tid * 16);
        cp_commit();
    };

    // B loader: 4 float4 per thread (rows tid>>5 + 8i, float4-col tid&31)
    const int b_row  = tid >> 5;
    const int b_col4 = tid & 31;

    // ldmatrix per-lane address component
    const uint32_t ldsm_lane = (uint32_t)(((lane & 7) + ((lane >> 3) & 1) * 8) * B_PITCH
                                          + (lane >> 4) * 16);

    float acc[4][4][4];
    #pragma unroll
    for (int mi = 0; mi < 4; mi++)
        #pragma unroll
        for (int ni = 0; ni < 4; ni++)
            #pragma unroll
            for (int q = 0; q < 4; q++) acc[mi][ni][q] = 0.0f;

    float4 rb[4];
    auto ldgB = [&](int kb) {
        #pragma unroll
        for (int i = 0; i < 4; i++)
            rb[i] = *(const float4*)(Bg + (size_t)(kb * KC + b_row + 8 * i) * HW_DIM
                                     + 4 * b_col4);
    };
    auto stsB = [&](int buf) {
        const uint32_t base = sm_base + B_OFF + buf * B_STAGE
                            + (uint32_t)(b_row * B_PITCH + b_col4 * 8);
        #pragma unroll
        for (int i = 0; i < 4; i++) {
            uint32_t lo = h2pack(rb[i].x, rb[i].y);
            uint32_t hi = h2pack(rb[i].z, rb[i].w);
            asm volatile("st.shared.v2.u32 [%0], {%1, %2};"
                         :: "r"(base + i * (8u * B_PITCH)), "r"(lo), "r"(hi));
        }
    };

    // ---- prologue ----
    issueA(0, 0);
    issueA(1, 1);
    ldgB(0);
    stsB(0);
    asm volatile("cp.async.wait_group 1;");
    __syncthreads();

    #pragma unroll 1
    for (int kb = 0; kb < NKB; kb++) {
        const int s   = kb % 3;
        const int buf = kb & 1;

        if (kb < NKB - 1) ldgB(kb + 1);
        if (kb + 2 < NKB) issueA(kb + 2, (kb + 2) % 3);

        const uint32_t Ast = sm_base + (uint32_t)(s * A_STAGE);
        const uint32_t Bst = sm_base + B_OFF + buf * B_STAGE;
        #pragma unroll
        for (int ks = 0; ks < 2; ks++) {
            uint4 a[4];
            #pragma unroll
            for (int mi = 0; mi < 4; mi++) {
                uint32_t addr = Ast + (uint32_t)((((wm * 4 + mi) * 2 + ks) * 32 + lane) * 16);
                asm volatile("ld.shared.v4.u32 {%0,%1,%2,%3}, [%4];"
                             : "=r"(a[mi].x), "=r"(a[mi].y), "=r"(a[mi].z), "=r"(a[mi].w)
                             : "r"(addr));
            }
            #pragma unroll
            for (int pair = 0; pair < 2; pair++) {
                uint32_t r0, r1, r2, r3;
                ldsm_x4_t(r0, r1, r2, r3,
                          Bst + (uint32_t)(ks * 16 * B_PITCH
                                           + (wn * 32 + pair * 16) * 2) + ldsm_lane);
                #pragma unroll
                for (int mi = 0; mi < 4; mi++) {
                    mma_f16(acc[mi][pair * 2 + 0], a[mi].x, a[mi].y, a[mi].z, a[mi].w, r0, r1);
                    mma_f16(acc[mi][pair * 2 + 1], a[mi].x, a[mi].y, a[mi].z, a[mi].w, r2, r3);
                }
            }
        }

        if (kb < NKB - 1) {
            stsB(buf ^ 1);
            if (kb == NKB - 2) asm volatile("cp.async.wait_group 0;");
            else               asm volatile("cp.async.wait_group 1;");
            __syncthreads();
        }
    }

    // ---- epilogue ----
    float* Og = out + (size_t)b * C_DIM * HW_DIM + (size_t)(h * M_TILE) * HW_DIM + p0;
    #pragma unroll
    for (int mi = 0; mi < 4; mi++) {
        int c0 = wm * 64 + mi * 16 + g;
        #pragma unroll
        for (int ni = 0; ni < 4; ni++) {
            int p = wn * 32 + ni * 8 + 2 * tg;
            *(float2*)(Og + (size_t)c0 * HW_DIM + p) =
                make_float2(acc[mi][ni][0], acc[mi][ni][1]);
            *(float2*)(Og + (size_t)(c0 + 8) * HW_DIM + p) =
                make_float2(acc[mi][ni][2], acc[mi][ni][3]);
        }
    }
}

// ---------------------------------------------------------------------------
extern "C" void kernel_launch(void* const* d_in, const int* in_sizes, int n_in,
                              void* d_out, int out_size) {
    const float* feat = (const float*)d_in[0];   // [B, C, H, W] fp32
    const float* cb   = (const float*)d_in[1];   // [N, C] fp32
    float* out        = (float*)d_out;           // [B, C, H, W] fp32

    norm_kernel<<<NCODES, C_DIM>>>(cb);
    mmat_kernel<<<dim3(16, 16), 256>>>(cb);

    cudaFuncSetAttribute(gemm_kernel,
                         cudaFuncAttributeMaxDynamicSharedMemorySize, SMEM_BYTES);
    gemm_kernel<<<dim3(2, HW_DIM / N_TILE, BATCH), 256, SMEM_BYTES>>>(feat, out);
}